// round 13
// baseline (speedup 1.0000x reference)
#include <cuda_runtime.h>
#include <math.h>

// Problem constants
#define BB 2
#define NN 16384
#define CC 8
#define DD 256
#define HH 64
#define WW 64

// Scratch (device globals: allocation-free)
__device__ float g_t[(size_t)BB * NN * DD];      // t = LN(q) @ Wqk + bqk, scaled 1/16
__device__ float g_u[(size_t)BB * NN * DD];      // u = sum_c attn*sampled
__device__ float g_s[(size_t)BB * NN];           // sum of attn per row (0 or 1)
__device__ float g_Wqk[DD * DD];                 // Wq @ Wkv[:,:D]^T
__device__ float g_Wvo[DD * DD];                 // Wkv[:,D:] @ Wo
__device__ float g_bqk[DD];
__device__ float g_bvo[DD];

__device__ __forceinline__ void cp16(void* smem_dst, const void* gmem_src) {
    unsigned s = (unsigned)__cvta_generic_to_shared(smem_dst);
    asm volatile("cp.async.cg.shared.global [%0], [%1], 16;" :: "r"(s), "l"(gmem_src));
}
#define CP_COMMIT() asm volatile("cp.async.commit_group;")

// ---------------------------------------------------------------------------
// Weight folding (fp32, exact). 513 blocks x 256 threads.
// ---------------------------------------------------------------------------
__global__ void fold_kernel(const float* __restrict__ Wq,
                            const float* __restrict__ bq,
                            const float* __restrict__ Wkv,
                            const float* __restrict__ bkv,
                            const float* __restrict__ Wo) {
    __shared__ float srow[DD];
    int bidx = blockIdx.x;
    int tid = threadIdx.x;

    if (bidx < 256) {
        srow[tid] = Wq[(size_t)bidx * DD + tid];
        __syncthreads();
        float acc = 0.f;
        const float* wr = Wkv + (size_t)tid * (2 * DD);
        #pragma unroll 4
        for (int d = 0; d < DD; d++) acc += srow[d] * wr[d];
        g_Wqk[(size_t)bidx * DD + tid] = acc;
    } else if (bidx < 512) {
        int i = bidx - 256;
        srow[tid] = Wkv[(size_t)i * (2 * DD) + DD + tid];
        __syncthreads();
        float acc = 0.f;
        #pragma unroll 4
        for (int k = 0; k < DD; k++) acc += srow[k] * Wo[(size_t)k * DD + tid];
        g_Wvo[(size_t)i * DD + tid] = acc;
    } else {
        float a1 = 0.f, a2 = 0.f;
        const float* wr = Wkv + (size_t)tid * (2 * DD);
        #pragma unroll 4
        for (int d = 0; d < DD; d++) a1 += wr[d] * bq[d];
        #pragma unroll 4
        for (int k = 0; k < DD; k++) a2 += bkv[DD + k] * Wo[(size_t)k * DD + tid];
        g_bqk[tid] = a1;
        g_bvo[tid] = a2;
    }
}

// ---------------------------------------------------------------------------
// TF32 tensor-core GEMM, BM=64 BN=128 BK=16, 256 threads (8 warps, 32x32 warp
// tiles), 3-stage cp.async pipeline, one __syncthreads per k-tile.
// Raw fp32 into tf32 MMA. A stored [m][k] LDA=20. Optional fused row-LN on A.
// K must be 256. 3 CTAs/SM.
// Epilogue: C = scale*(A@W + bias [+ svec[r]*bvec2[c]]) [+ resid].
// ---------------------------------------------------------------------------
template <bool DO_LN>
__global__ void __launch_bounds__(256, 3)
gemm3_kernel(const float* __restrict__ A, const float* __restrict__ W,
             const float* __restrict__ bias, const float* __restrict__ resid,
             const float* __restrict__ svec, const float* __restrict__ bvec2,
             const float* __restrict__ gamma, const float* __restrict__ beta,
             float scale, float* __restrict__ Cm, int M, int K, int Nc) {
    const int BK = 16, LDA = 20, LDB = 136, NT = 16;   // NT = K/BK, K==256
    __shared__ unsigned As[3][64][LDA];
    __shared__ unsigned Bs[3][BK][LDB];
    __shared__ float sg[DD], sb[DD];

    int tid = threadIdx.x;
    int lane = tid & 31;
    int wid = tid >> 5;
    int wm = wid >> 2;
    int wn = wid & 3;
    int g = lane >> 2;
    int tg = lane & 3;

    size_t row0 = (size_t)blockIdx.y * 64;
    size_t col0 = (size_t)blockIdx.x * 128;

    int a_m = tid >> 2;
    int a_kq = tid & 3;
    int b_kk = tid >> 5;
    int b_nq = tid & 31;

    const float* Aptr = A + (row0 + a_m) * (size_t)K + a_kq * 4;
    const float* Bptr = W + (size_t)b_kk * Nc + col0 + b_nq * 4;

    float mu = 0.f, rs = 0.f;
    if (DO_LN) {
        sg[tid] = gamma[tid];
        sb[tid] = beta[tid];
        const float4* rp = (const float4*)(A + (row0 + a_m) * (size_t)K + a_kq * 64);
        float s = 0.f, s2 = 0.f;
        #pragma unroll
        for (int i = 0; i < 16; i++) {
            float4 v = rp[i];
            s += v.x + v.y + v.z + v.w;
            s2 += v.x * v.x + v.y * v.y + v.z * v.z + v.w * v.w;
        }
        s += __shfl_xor_sync(0xFFFFFFFFu, s, 1);
        s += __shfl_xor_sync(0xFFFFFFFFu, s, 2);
        s2 += __shfl_xor_sync(0xFFFFFFFFu, s2, 1);
        s2 += __shfl_xor_sync(0xFFFFFFFFu, s2, 2);
        mu = s * (1.f / (float)DD);
        rs = rsqrtf(s2 * (1.f / (float)DD) - mu * mu + 1e-5f);
        __syncthreads();
    }

    float acc[2][4][4];
    #pragma unroll
    for (int i = 0; i < 2; i++)
        #pragma unroll
        for (int j = 0; j < 4; j++)
            #pragma unroll
            for (int r = 0; r < 4; r++) acc[i][j][r] = 0.f;

#define LOADB(t, buf)                                                        \
    do {                                                                     \
        cp16(&Bs[buf][b_kk][b_nq * 4], Bptr + (size_t)((t) * BK) * Nc);      \
        cp16(&Bs[buf][b_kk + 8][b_nq * 4],                                   \
             Bptr + (size_t)((t) * BK + 8) * Nc);                            \
    } while (0)

#define STORA_LN(buf, av, t)                                                 \
    do {                                                                     \
        int kc = a_kq * 4, kg = (t) * BK + kc;                               \
        As[buf][a_m][kc + 0] =                                               \
            __float_as_uint(((av).x - mu) * rs * sg[kg + 0] + sb[kg + 0]);   \
        As[buf][a_m][kc + 1] =                                               \
            __float_as_uint(((av).y - mu) * rs * sg[kg + 1] + sb[kg + 1]);   \
        As[buf][a_m][kc + 2] =                                               \
            __float_as_uint(((av).z - mu) * rs * sg[kg + 2] + sb[kg + 2]);   \
        As[buf][a_m][kc + 3] =                                               \
            __float_as_uint(((av).w - mu) * rs * sg[kg + 3] + sb[kg + 3]);   \
    } while (0)

    // ---- prologue: tiles 0 and 1 committed
    if (DO_LN) {
        float4 av0 = *(const float4*)(Aptr);
        float4 av1 = *(const float4*)(Aptr + BK);
        LOADB(0, 0); CP_COMMIT();
        LOADB(1, 1); CP_COMMIT();
        STORA_LN(0, av0, 0);
        STORA_LN(1, av1, 1);
    } else {
        cp16(&As[0][a_m][a_kq * 4], Aptr);
        LOADB(0, 0); CP_COMMIT();
        cp16(&As[1][a_m][a_kq * 4], Aptr + BK);
        LOADB(1, 1); CP_COMMIT();
    }

    for (int kt = 0; kt < NT; kt++) {
        int pf = kt + 2;
        if (kt < NT - 1) asm volatile("cp.async.wait_group 1;");
        else             asm volatile("cp.async.wait_group 0;");
        __syncthreads();   // all warps done reading buf (kt-1)%3

        float4 av;
        if (pf < NT) {
            int buf = pf % 3;
            if (DO_LN) av = *(const float4*)(Aptr + pf * BK);
            else cp16(&As[buf][a_m][a_kq * 4], Aptr + pf * BK);
            LOADB(pf, buf);
            CP_COMMIT();
        }

        int cur = kt % 3;
        #pragma unroll
        for (int ks = 0; ks < 2; ks++) {
            int kb = ks * 8;
            unsigned a[2][4], b[4][2];
            #pragma unroll
            for (int mt = 0; mt < 2; mt++) {
                int m = wm * 32 + mt * 16 + g;
                a[mt][0] = As[cur][m][kb + tg];
                a[mt][1] = As[cur][m + 8][kb + tg];
                a[mt][2] = As[cur][m][kb + tg + 4];
                a[mt][3] = As[cur][m + 8][kb + tg + 4];
            }
            #pragma unroll
            for (int nt = 0; nt < 4; nt++) {
                int n = wn * 32 + nt * 8 + g;
                b[nt][0] = Bs[cur][kb + tg][n];
                b[nt][1] = Bs[cur][kb + tg + 4][n];
            }
            #pragma unroll
            for (int mt = 0; mt < 2; mt++)
                #pragma unroll
                for (int nt = 0; nt < 4; nt++) {
                    asm volatile(
                        "mma.sync.aligned.m16n8k8.row.col.f32.tf32.tf32.f32 "
                        "{%0,%1,%2,%3}, {%4,%5,%6,%7}, {%8,%9}, {%0,%1,%2,%3};\n"
                        : "+f"(acc[mt][nt][0]), "+f"(acc[mt][nt][1]),
                          "+f"(acc[mt][nt][2]), "+f"(acc[mt][nt][3])
                        : "r"(a[mt][0]), "r"(a[mt][1]), "r"(a[mt][2]), "r"(a[mt][3]),
                          "r"(b[nt][0]), "r"(b[nt][1]));
                }
        }

        if (DO_LN && pf < NT) STORA_LN(pf % 3, av, pf);
    }

    // ---- epilogue
    #pragma unroll
    for (int mt = 0; mt < 2; mt++) {
        size_t r = row0 + wm * 32 + mt * 16 + g;
        #pragma unroll
        for (int nt = 0; nt < 4; nt++) {
            size_t c = col0 + wn * 32 + nt * 8 + tg * 2;
            float2 bb = *(const float2*)(bias + c);
            float2 v0, v1;
            v0.x = acc[mt][nt][0] + bb.x;
            v0.y = acc[mt][nt][1] + bb.y;
            v1.x = acc[mt][nt][2] + bb.x;
            v1.y = acc[mt][nt][3] + bb.y;
            if (svec) {
                float2 b2 = *(const float2*)(bvec2 + c);
                float s0 = svec[r], s1 = svec[r + 8];
                v0.x += s0 * b2.x; v0.y += s0 * b2.y;
                v1.x += s1 * b2.x; v1.y += s1 * b2.y;
            }
            v0.x *= scale; v0.y *= scale; v1.x *= scale; v1.y *= scale;
            if (resid) {
                float2 r0 = *(const float2*)(resid + r * Nc + c);
                float2 r1 = *(const float2*)(resid + (r + 8) * Nc + c);
                v0.x += r0.x; v0.y += r0.y;
                v1.x += r1.x; v1.y += r1.y;
            }
            *(float2*)(Cm + r * Nc + c) = v0;
            *(float2*)(Cm + (r + 8) * Nc + c) = v1;
        }
    }
#undef LOADB
#undef STORA_LN
}

// ---------------------------------------------------------------------------
// Warp-per-row fused attention, TWO-PHASE:
//   Phase A: per valid channel, gather + blended dot -> partial pd[c]
//            (no samples kept: all channels' loads independent, MLP ~64)
//   Reduce:  ONE interleaved 5-step butterfly over all 8 pd[] (chains pipeline:
//            ~170 cyc total vs ~520 for per-channel serial chains)
//   Phase B: weights e[c]; re-gather (L1 hits) and accumulate U += e*s.
// No max subtraction (scores bounded: t pre-scaled by 1/sqrt(D)).
// 256 threads = 8 rows/block; zero smem, zero barriers.
// ---------------------------------------------------------------------------
__global__ void __launch_bounds__(256, 3)
fused_attn_warp(const float* __restrict__ feat,
                const float* __restrict__ coords,
                const int* __restrict__ vmask,
                const float* __restrict__ t,
                float* __restrict__ u,
                float* __restrict__ s_out) {
    int gw = (blockIdx.x << 3) | (threadIdx.x >> 5);   // global warp = row bn
    int lane = threadIdx.x & 31;
    int b = gw >> 14;              // NN = 16384
    int n = gw & (NN - 1);

    // hoist all 8 mask loads (independent LDGs)
    unsigned mbits = 0;
    #pragma unroll
    for (int c = 0; c < CC; c++)
        mbits |= (vmask[((size_t)(b * CC + c)) * NN + n] ? 1u : 0u) << c;

    const float4* t4 = (const float4*)(t + (size_t)gw * DD);
    float4 tv0 = t4[lane];
    float4 tv1 = t4[lane + 32];

    // ---- Phase A: partial blended dots, all channels independent
    float pd[CC];
    #pragma unroll
    for (int c = 0; c < CC; c++) {
        pd[c] = 0.f;
        if (!((mbits >> c) & 1u)) continue;

        const float* pc = coords + ((size_t)(b * CC + c) * NN + n) * 2;
        float xf = (pc[0] + 1.f) * 0.5f * (float)(WW - 1);
        float yf = (pc[1] + 1.f) * 0.5f * (float)(HH - 1);
        float x0f = floorf(xf), y0f = floorf(yf);
        float wx = xf - x0f, wy = yf - y0f;
        int x0 = (int)x0f, y0 = (int)y0f;
        float w00 = (1.f - wy) * (1.f - wx);
        float w01 = (1.f - wy) * wx;
        float w10 = wy * (1.f - wx);
        float w11 = wy * wx;
        if (!((x0 >= 0) & (x0 < WW) & (y0 >= 0) & (y0 < HH))) w00 = 0.f;
        if (!((x0 + 1 >= 0) & (x0 + 1 < WW) & (y0 >= 0) & (y0 < HH))) w01 = 0.f;
        if (!((x0 >= 0) & (x0 < WW) & (y0 + 1 >= 0) & (y0 + 1 < HH))) w10 = 0.f;
        if (!((x0 + 1 >= 0) & (x0 + 1 < WW) & (y0 + 1 >= 0) & (y0 + 1 < HH))) w11 = 0.f;
        int xc0 = min(max(x0, 0), WW - 1);
        int xc1 = min(max(x0 + 1, 0), WW - 1);
        int yc0 = min(max(y0, 0), HH - 1);
        int yc1 = min(max(y0 + 1, 0), HH - 1);

        size_t fbase = (size_t)(b * CC + c) * HH * WW;
        const float4* f00 = (const float4*)(feat + (fbase + (size_t)yc0 * WW + xc0) * DD);
        const float4* f01 = (const float4*)(feat + (fbase + (size_t)yc0 * WW + xc1) * DD);
        const float4* f10 = (const float4*)(feat + (fbase + (size_t)yc1 * WW + xc0) * DD);
        const float4* f11 = (const float4*)(feat + (fbase + (size_t)yc1 * WW + xc1) * DD);

        float4 a00 = f00[lane], a01 = f01[lane], a10 = f10[lane], a11 = f11[lane];
        float4 b00 = f00[lane + 32], b01 = f01[lane + 32],
               b10 = f10[lane + 32], b11 = f11[lane + 32];

        // per-corner partial dots, then blend scalars (same math as blending first)
        float d00 = a00.x * tv0.x + a00.y * tv0.y + a00.z * tv0.z + a00.w * tv0.w
                  + b00.x * tv1.x + b00.y * tv1.y + b00.z * tv1.z + b00.w * tv1.w;
        float d01 = a01.x * tv0.x + a01.y * tv0.y + a01.z * tv0.z + a01.w * tv0.w
                  + b01.x * tv1.x + b01.y * tv1.y + b01.z * tv1.z + b01.w * tv1.w;
        float d10 = a10.x * tv0.x + a10.y * tv0.y + a10.z * tv0.z + a10.w * tv0.w
                  + b10.x * tv1.x + b10.y * tv1.y + b10.z * tv1.z + b10.w * tv1.w;
        float d11 = a11.x * tv0.x + a11.y * tv0.y + a11.z * tv0.z + a11.w * tv0.w
                  + b11.x * tv1.x + b11.y * tv1.y + b11.z * tv1.z + b11.w * tv1.w;
        pd[c] = w00 * d00 + w01 * d01 + w10 * d10 + w11 * d11;
    }

    // ---- interleaved butterfly: all 8 chains share the 5 dependency steps
    #pragma unroll
    for (int o = 16; o > 0; o >>= 1) {
        #pragma unroll
        for (int c = 0; c < CC; c++)
            pd[c] += __shfl_xor_sync(0xFFFFFFFFu, pd[c], o);
    }

    // ---- softmax weights (no max subtraction; scores bounded)
    float e[CC];
    float den = 0.f;
    #pragma unroll
    for (int c = 0; c < CC; c++) {
        e[c] = ((mbits >> c) & 1u) ? __expf(pd[c]) : 0.f;
        den += e[c];
    }
    float inv = (den > 0.f) ? (1.f / den) : 0.f;

    // ---- Phase B: re-gather (L1-hot) and accumulate weighted samples
    float4 U0 = {0.f, 0.f, 0.f, 0.f}, U1 = {0.f, 0.f, 0.f, 0.f};
    #pragma unroll
    for (int c = 0; c < CC; c++) {
        if (!((mbits >> c) & 1u)) continue;
        float wgt = e[c] * inv;

        const float* pc = coords + ((size_t)(b * CC + c) * NN + n) * 2;
        float xf = (pc[0] + 1.f) * 0.5f * (float)(WW - 1);
        float yf = (pc[1] + 1.f) * 0.5f * (float)(HH - 1);
        float x0f = floorf(xf), y0f = floorf(yf);
        float wx = xf - x0f, wy = yf - y0f;
        int x0 = (int)x0f, y0 = (int)y0f;
        float w00 = (1.f - wy) * (1.f - wx) * wgt;
        float w01 = (1.f - wy) * wx * wgt;
        float w10 = wy * (1.f - wx) * wgt;
        float w11 = wy * wx * wgt;
        if (!((x0 >= 0) & (x0 < WW) & (y0 >= 0) & (y0 < HH))) w00 = 0.f;
        if (!((x0 + 1 >= 0) & (x0 + 1 < WW) & (y0 >= 0) & (y0 < HH))) w01 = 0.f;
        if (!((x0 >= 0) & (x0 < WW) & (y0 + 1 >= 0) & (y0 + 1 < HH))) w10 = 0.f;
        if (!((x0 + 1 >= 0) & (x0 + 1 < WW) & (y0 + 1 >= 0) & (y0 + 1 < HH))) w11 = 0.f;
        int xc0 = min(max(x0, 0), WW - 1);
        int xc1 = min(max(x0 + 1, 0), WW - 1);
        int yc0 = min(max(y0, 0), HH - 1);
        int yc1 = min(max(y0 + 1, 0), HH - 1);

        size_t fbase = (size_t)(b * CC + c) * HH * WW;
        const float4* f00 = (const float4*)(feat + (fbase + (size_t)yc0 * WW + xc0) * DD);
        const float4* f01 = (const float4*)(feat + (fbase + (size_t)yc0 * WW + xc1) * DD);
        const float4* f10 = (const float4*)(feat + (fbase + (size_t)yc1 * WW + xc0) * DD);
        const float4* f11 = (const float4*)(feat + (fbase + (size_t)yc1 * WW + xc1) * DD);

        float4 a00 = f00[lane], a01 = f01[lane], a10 = f10[lane], a11 = f11[lane];
        float4 b00 = f00[lane + 32], b01 = f01[lane + 32],
               b10 = f10[lane + 32], b11 = f11[lane + 32];

        U0.x += w00 * a00.x + w01 * a01.x + w10 * a10.x + w11 * a11.x;
        U0.y += w00 * a00.y + w01 * a01.y + w10 * a10.y + w11 * a11.y;
        U0.z += w00 * a00.z + w01 * a01.z + w10 * a10.z + w11 * a11.z;
        U0.w += w00 * a00.w + w01 * a01.w + w10 * a10.w + w11 * a11.w;
        U1.x += w00 * b00.x + w01 * b01.x + w10 * b10.x + w11 * b11.x;
        U1.y += w00 * b00.y + w01 * b01.y + w10 * b10.y + w11 * b11.y;
        U1.z += w00 * b00.z + w01 * b01.z + w10 * b10.z + w11 * b11.z;
        U1.w += w00 * b00.w + w01 * b01.w + w10 * b10.w + w11 * b11.w;
    }

    float4* u4 = (float4*)(u + (size_t)gw * DD);
    u4[lane] = U0;
    u4[lane + 32] = U1;
    if (lane == 0) s_out[gw] = (den > 0.f) ? 1.f : 0.f;
}

// ---------------------------------------------------------------------------
// Launch
// ---------------------------------------------------------------------------
extern "C" void kernel_launch(void* const* d_in, const int* in_sizes, int n_in,
                              void* d_out, int out_size) {
    const float* queries = (const float*)d_in[0];
    const float* feat    = (const float*)d_in[1];
    const float* coords  = (const float*)d_in[2];
    const int*   vmask   = (const int*)d_in[3];
    const float* Wq      = (const float*)d_in[4];
    const float* bq      = (const float*)d_in[5];
    const float* Wkv     = (const float*)d_in[6];
    const float* bkv     = (const float*)d_in[7];
    const float* Wo      = (const float*)d_in[8];
    const float* bo      = (const float*)d_in[9];
    const float* gamma   = (const float*)d_in[10];
    const float* beta    = (const float*)d_in[11];
    float* out = (float*)d_out;

    float *p_t, *p_u, *p_s, *p_Wqk, *p_Wvo, *p_bqk, *p_bvo;
    cudaGetSymbolAddress((void**)&p_t, g_t);
    cudaGetSymbolAddress((void**)&p_u, g_u);
    cudaGetSymbolAddress((void**)&p_s, g_s);
    cudaGetSymbolAddress((void**)&p_Wqk, g_Wqk);
    cudaGetSymbolAddress((void**)&p_Wvo, g_Wvo);
    cudaGetSymbolAddress((void**)&p_bqk, g_bqk);
    cudaGetSymbolAddress((void**)&p_bvo, g_bvo);

    const int Mq = BB * NN;   // 32768

    fold_kernel<<<513, 256>>>(Wq, bq, Wkv, bkv, Wo);
    // t = LN(queries) @ Wqk + bqk, scaled by 1/16, LN fused into A-load
    gemm3_kernel<true><<<dim3(DD / 128, Mq / 64), 256>>>(
        queries, p_Wqk, p_bqk, nullptr, nullptr, nullptr,
        gamma, beta, 0.0625f, p_t, Mq, DD, DD);
    // fused sample + attention (warp per row, two-phase) -> u, s
    fused_attn_warp<<<Mq / 8, 256>>>(feat, coords, vmask, p_t, p_u, p_s);
    // out = queries + u @ Wvo + s*bvo + bo
    gemm3_kernel<false><<<dim3(DD / 128, Mq / 64), 256>>>(
        p_u, p_Wvo, bo, queries, p_s, p_bvo,
        nullptr, nullptr, 1.0f, out, Mq, DD, DD);
}

// round 14
// speedup vs baseline: 1.0230x; 1.0230x over previous
#include <cuda_runtime.h>
#include <math.h>

// Problem constants
#define BB 2
#define NN 16384
#define CC 8
#define DD 256
#define HH 64
#define WW 64

// Scratch (device globals: allocation-free)
__device__ float g_t[(size_t)BB * NN * DD];      // t = LN(q) @ Wqk + bqk, scaled 1/16
__device__ float g_u[(size_t)BB * NN * DD];      // u = sum_c attn*sampled
__device__ float g_s[(size_t)BB * NN];           // sum of attn per row (0 or 1)
__device__ float g_Wqk[DD * DD];                 // Wq @ Wkv[:,:D]^T
__device__ float g_Wvo[DD * DD];                 // Wkv[:,D:] @ Wo
__device__ float g_bqk[DD];
__device__ float g_bvo[DD];

__device__ __forceinline__ void cp16(void* smem_dst, const void* gmem_src) {
    unsigned s = (unsigned)__cvta_generic_to_shared(smem_dst);
    asm volatile("cp.async.cg.shared.global [%0], [%1], 16;" :: "r"(s), "l"(gmem_src));
}
#define CP_COMMIT() asm volatile("cp.async.commit_group;")

// ---------------------------------------------------------------------------
// Weight folding (fp32, exact). 513 blocks x 256 threads.
// ---------------------------------------------------------------------------
__global__ void fold_kernel(const float* __restrict__ Wq,
                            const float* __restrict__ bq,
                            const float* __restrict__ Wkv,
                            const float* __restrict__ bkv,
                            const float* __restrict__ Wo) {
    __shared__ float srow[DD];
    int bidx = blockIdx.x;
    int tid = threadIdx.x;

    if (bidx < 256) {
        srow[tid] = Wq[(size_t)bidx * DD + tid];
        __syncthreads();
        float acc = 0.f;
        const float* wr = Wkv + (size_t)tid * (2 * DD);
        #pragma unroll 4
        for (int d = 0; d < DD; d++) acc += srow[d] * wr[d];
        g_Wqk[(size_t)bidx * DD + tid] = acc;
    } else if (bidx < 512) {
        int i = bidx - 256;
        srow[tid] = Wkv[(size_t)i * (2 * DD) + DD + tid];
        __syncthreads();
        float acc = 0.f;
        #pragma unroll 4
        for (int k = 0; k < DD; k++) acc += srow[k] * Wo[(size_t)k * DD + tid];
        g_Wvo[(size_t)i * DD + tid] = acc;
    } else {
        float a1 = 0.f, a2 = 0.f;
        const float* wr = Wkv + (size_t)tid * (2 * DD);
        #pragma unroll 4
        for (int d = 0; d < DD; d++) a1 += wr[d] * bq[d];
        #pragma unroll 4
        for (int k = 0; k < DD; k++) a2 += bkv[DD + k] * Wo[(size_t)k * DD + tid];
        g_bqk[tid] = a1;
        g_bvo[tid] = a2;
    }
}

// ---------------------------------------------------------------------------
// TF32 tensor-core GEMM, BM=64 BN=128 BK=16, 256 threads (8 warps, 32x32 warp
// tiles), 3-stage cp.async pipeline, one __syncthreads per k-tile.
// Raw fp32 into tf32 MMA. A stored [m][k] LDA=20. Optional fused row-LN on A.
// K must be 256. 3 CTAs/SM.
// Epilogue: C = scale*(A@W + bias [+ svec[r]*bvec2[c]]) [+ resid].
// ---------------------------------------------------------------------------
template <bool DO_LN>
__global__ void __launch_bounds__(256, 3)
gemm3_kernel(const float* __restrict__ A, const float* __restrict__ W,
             const float* __restrict__ bias, const float* __restrict__ resid,
             const float* __restrict__ svec, const float* __restrict__ bvec2,
             const float* __restrict__ gamma, const float* __restrict__ beta,
             float scale, float* __restrict__ Cm, int M, int K, int Nc) {
    const int BK = 16, LDA = 20, LDB = 136, NT = 16;   // NT = K/BK, K==256
    __shared__ unsigned As[3][64][LDA];
    __shared__ unsigned Bs[3][BK][LDB];
    __shared__ float sg[DD], sb[DD];

    int tid = threadIdx.x;
    int lane = tid & 31;
    int wid = tid >> 5;
    int wm = wid >> 2;
    int wn = wid & 3;
    int g = lane >> 2;
    int tg = lane & 3;

    size_t row0 = (size_t)blockIdx.y * 64;
    size_t col0 = (size_t)blockIdx.x * 128;

    int a_m = tid >> 2;
    int a_kq = tid & 3;
    int b_kk = tid >> 5;
    int b_nq = tid & 31;

    const float* Aptr = A + (row0 + a_m) * (size_t)K + a_kq * 4;
    const float* Bptr = W + (size_t)b_kk * Nc + col0 + b_nq * 4;

    float mu = 0.f, rs = 0.f;
    if (DO_LN) {
        sg[tid] = gamma[tid];
        sb[tid] = beta[tid];
        const float4* rp = (const float4*)(A + (row0 + a_m) * (size_t)K + a_kq * 64);
        float s = 0.f, s2 = 0.f;
        #pragma unroll
        for (int i = 0; i < 16; i++) {
            float4 v = rp[i];
            s += v.x + v.y + v.z + v.w;
            s2 += v.x * v.x + v.y * v.y + v.z * v.z + v.w * v.w;
        }
        s += __shfl_xor_sync(0xFFFFFFFFu, s, 1);
        s += __shfl_xor_sync(0xFFFFFFFFu, s, 2);
        s2 += __shfl_xor_sync(0xFFFFFFFFu, s2, 1);
        s2 += __shfl_xor_sync(0xFFFFFFFFu, s2, 2);
        mu = s * (1.f / (float)DD);
        rs = rsqrtf(s2 * (1.f / (float)DD) - mu * mu + 1e-5f);
        __syncthreads();
    }

    float acc[2][4][4];
    #pragma unroll
    for (int i = 0; i < 2; i++)
        #pragma unroll
        for (int j = 0; j < 4; j++)
            #pragma unroll
            for (int r = 0; r < 4; r++) acc[i][j][r] = 0.f;

#define LOADB(t, buf)                                                        \
    do {                                                                     \
        cp16(&Bs[buf][b_kk][b_nq * 4], Bptr + (size_t)((t) * BK) * Nc);      \
        cp16(&Bs[buf][b_kk + 8][b_nq * 4],                                   \
             Bptr + (size_t)((t) * BK + 8) * Nc);                            \
    } while (0)

#define STORA_LN(buf, av, t)                                                 \
    do {                                                                     \
        int kc = a_kq * 4, kg = (t) * BK + kc;                               \
        As[buf][a_m][kc + 0] =                                               \
            __float_as_uint(((av).x - mu) * rs * sg[kg + 0] + sb[kg + 0]);   \
        As[buf][a_m][kc + 1] =                                               \
            __float_as_uint(((av).y - mu) * rs * sg[kg + 1] + sb[kg + 1]);   \
        As[buf][a_m][kc + 2] =                                               \
            __float_as_uint(((av).z - mu) * rs * sg[kg + 2] + sb[kg + 2]);   \
        As[buf][a_m][kc + 3] =                                               \
            __float_as_uint(((av).w - mu) * rs * sg[kg + 3] + sb[kg + 3]);   \
    } while (0)

    // ---- prologue: tiles 0 and 1 committed
    if (DO_LN) {
        float4 av0 = *(const float4*)(Aptr);
        float4 av1 = *(const float4*)(Aptr + BK);
        LOADB(0, 0); CP_COMMIT();
        LOADB(1, 1); CP_COMMIT();
        STORA_LN(0, av0, 0);
        STORA_LN(1, av1, 1);
    } else {
        cp16(&As[0][a_m][a_kq * 4], Aptr);
        LOADB(0, 0); CP_COMMIT();
        cp16(&As[1][a_m][a_kq * 4], Aptr + BK);
        LOADB(1, 1); CP_COMMIT();
    }

    for (int kt = 0; kt < NT; kt++) {
        int pf = kt + 2;
        if (kt < NT - 1) asm volatile("cp.async.wait_group 1;");
        else             asm volatile("cp.async.wait_group 0;");
        __syncthreads();   // all warps done reading buf (kt-1)%3

        float4 av;
        if (pf < NT) {
            int buf = pf % 3;
            if (DO_LN) av = *(const float4*)(Aptr + pf * BK);
            else cp16(&As[buf][a_m][a_kq * 4], Aptr + pf * BK);
            LOADB(pf, buf);
            CP_COMMIT();
        }

        int cur = kt % 3;
        #pragma unroll
        for (int ks = 0; ks < 2; ks++) {
            int kb = ks * 8;
            unsigned a[2][4], b[4][2];
            #pragma unroll
            for (int mt = 0; mt < 2; mt++) {
                int m = wm * 32 + mt * 16 + g;
                a[mt][0] = As[cur][m][kb + tg];
                a[mt][1] = As[cur][m + 8][kb + tg];
                a[mt][2] = As[cur][m][kb + tg + 4];
                a[mt][3] = As[cur][m + 8][kb + tg + 4];
            }
            #pragma unroll
            for (int nt = 0; nt < 4; nt++) {
                int n = wn * 32 + nt * 8 + g;
                b[nt][0] = Bs[cur][kb + tg][n];
                b[nt][1] = Bs[cur][kb + tg + 4][n];
            }
            #pragma unroll
            for (int mt = 0; mt < 2; mt++)
                #pragma unroll
                for (int nt = 0; nt < 4; nt++) {
                    asm volatile(
                        "mma.sync.aligned.m16n8k8.row.col.f32.tf32.tf32.f32 "
                        "{%0,%1,%2,%3}, {%4,%5,%6,%7}, {%8,%9}, {%0,%1,%2,%3};\n"
                        : "+f"(acc[mt][nt][0]), "+f"(acc[mt][nt][1]),
                          "+f"(acc[mt][nt][2]), "+f"(acc[mt][nt][3])
                        : "r"(a[mt][0]), "r"(a[mt][1]), "r"(a[mt][2]), "r"(a[mt][3]),
                          "r"(b[nt][0]), "r"(b[nt][1]));
                }
        }

        if (DO_LN && pf < NT) STORA_LN(pf % 3, av, pf);
    }

    // ---- epilogue
    #pragma unroll
    for (int mt = 0; mt < 2; mt++) {
        size_t r = row0 + wm * 32 + mt * 16 + g;
        #pragma unroll
        for (int nt = 0; nt < 4; nt++) {
            size_t c = col0 + wn * 32 + nt * 8 + tg * 2;
            float2 bb = *(const float2*)(bias + c);
            float2 v0, v1;
            v0.x = acc[mt][nt][0] + bb.x;
            v0.y = acc[mt][nt][1] + bb.y;
            v1.x = acc[mt][nt][2] + bb.x;
            v1.y = acc[mt][nt][3] + bb.y;
            if (svec) {
                float2 b2 = *(const float2*)(bvec2 + c);
                float s0 = svec[r], s1 = svec[r + 8];
                v0.x += s0 * b2.x; v0.y += s0 * b2.y;
                v1.x += s1 * b2.x; v1.y += s1 * b2.y;
            }
            v0.x *= scale; v0.y *= scale; v1.x *= scale; v1.y *= scale;
            if (resid) {
                float2 r0 = *(const float2*)(resid + r * Nc + c);
                float2 r1 = *(const float2*)(resid + (r + 8) * Nc + c);
                v0.x += r0.x; v0.y += r0.y;
                v1.x += r1.x; v1.y += r1.y;
            }
            *(float2*)(Cm + r * Nc + c) = v0;
            *(float2*)(Cm + (r + 8) * Nc + c) = v1;
        }
    }
#undef LOADB
#undef STORA_LN
}

// ---------------------------------------------------------------------------
// 2-warps-per-row fused attention. 256 threads = 4 rows x 2 warps.
// Warp half h handles channels [4h, 4h+4): gather + blend + dot + exp,
// accumulating UNNORMALIZED partials (den_h, U_h). Partials combined through
// smem with ONE __syncthreads per 4-row block; softmax normalization applied
// after combining (algebraically exact). Halves each warp's serial channel
// chain and doubles per-row loads in flight.
// No max subtraction (scores bounded: t pre-scaled by 1/sqrt(D)).
// ---------------------------------------------------------------------------
__global__ void __launch_bounds__(256, 3)
fused_attn_warp2(const float* __restrict__ feat,
                 const float* __restrict__ coords,
                 const int* __restrict__ vmask,
                 const float* __restrict__ t,
                 float* __restrict__ u,
                 float* __restrict__ s_out) {
    __shared__ float4 sU0[4][32];
    __shared__ float4 sU1[4][32];
    __shared__ float  sden[4];

    int wid = threadIdx.x >> 5;
    int lane = threadIdx.x & 31;
    int rl = wid >> 1;                  // row within block: 0..3
    int half = wid & 1;                 // 0: channels 0-3, 1: channels 4-7
    int gw = (blockIdx.x << 2) | rl;    // global row bn
    int b = gw >> 14;                   // NN = 16384
    int n = gw & (NN - 1);

    // hoist this half's 4 mask loads
    unsigned mbits = 0;
    #pragma unroll
    for (int i = 0; i < 4; i++) {
        int c = half * 4 + i;
        mbits |= (vmask[((size_t)(b * CC + c)) * NN + n] ? 1u : 0u) << i;
    }

    const float4* t4 = (const float4*)(t + (size_t)gw * DD);
    float4 tv0 = t4[lane];
    float4 tv1 = t4[lane + 32];

    float4 U0 = {0.f, 0.f, 0.f, 0.f}, U1 = {0.f, 0.f, 0.f, 0.f};
    float den = 0.f;

    #pragma unroll
    for (int i = 0; i < 4; i++) {
        if (!((mbits >> i) & 1u)) continue;   // warp-uniform skip
        int c = half * 4 + i;

        const float* pc = coords + ((size_t)(b * CC + c) * NN + n) * 2;
        float xf = (pc[0] + 1.f) * 0.5f * (float)(WW - 1);
        float yf = (pc[1] + 1.f) * 0.5f * (float)(HH - 1);
        float x0f = floorf(xf), y0f = floorf(yf);
        float wx = xf - x0f, wy = yf - y0f;
        int x0 = (int)x0f, y0 = (int)y0f;
        float w00 = (1.f - wy) * (1.f - wx);
        float w01 = (1.f - wy) * wx;
        float w10 = wy * (1.f - wx);
        float w11 = wy * wx;
        bool bx0 = (x0 >= 0) && (x0 < WW);
        bool bx1 = (x0 + 1 >= 0) && (x0 + 1 < WW);
        bool by0 = (y0 >= 0) && (y0 < HH);
        bool by1 = (y0 + 1 >= 0) && (y0 + 1 < HH);
        if (!(bx0 && by0)) w00 = 0.f;
        if (!(bx1 && by0)) w01 = 0.f;
        if (!(bx0 && by1)) w10 = 0.f;
        if (!(bx1 && by1)) w11 = 0.f;
        int xc0 = min(max(x0, 0), WW - 1);
        int xc1 = min(max(x0 + 1, 0), WW - 1);
        int yc0 = min(max(y0, 0), HH - 1);
        int yc1 = min(max(y0 + 1, 0), HH - 1);

        size_t fbase = (size_t)(b * CC + c) * HH * WW;
        const float4* f00 = (const float4*)(feat + (fbase + (size_t)yc0 * WW + xc0) * DD);
        const float4* f01 = (const float4*)(feat + (fbase + (size_t)yc0 * WW + xc1) * DD);
        const float4* f10 = (const float4*)(feat + (fbase + (size_t)yc1 * WW + xc0) * DD);
        const float4* f11 = (const float4*)(feat + (fbase + (size_t)yc1 * WW + xc1) * DD);

        float4 a00 = f00[lane], a01 = f01[lane], a10 = f10[lane], a11 = f11[lane];
        float4 b00 = f00[lane + 32], b01 = f01[lane + 32],
               b10 = f10[lane + 32], b11 = f11[lane + 32];

        float4 s0, s1;
        s0.x = w00 * a00.x; s0.y = w00 * a00.y; s0.z = w00 * a00.z; s0.w = w00 * a00.w;
        s0.x += w01 * a01.x; s0.y += w01 * a01.y; s0.z += w01 * a01.z; s0.w += w01 * a01.w;
        s0.x += w10 * a10.x; s0.y += w10 * a10.y; s0.z += w10 * a10.z; s0.w += w10 * a10.w;
        s0.x += w11 * a11.x; s0.y += w11 * a11.y; s0.z += w11 * a11.z; s0.w += w11 * a11.w;
        s1.x = w00 * b00.x; s1.y = w00 * b00.y; s1.z = w00 * b00.z; s1.w = w00 * b00.w;
        s1.x += w01 * b01.x; s1.y += w01 * b01.y; s1.z += w01 * b01.z; s1.w += w01 * b01.w;
        s1.x += w10 * b10.x; s1.y += w10 * b10.y; s1.z += w10 * b10.z; s1.w += w10 * b10.w;
        s1.x += w11 * b11.x; s1.y += w11 * b11.y; s1.z += w11 * b11.z; s1.w += w11 * b11.w;

        float pd = s0.x * tv0.x + s0.y * tv0.y + s0.z * tv0.z + s0.w * tv0.w
                 + s1.x * tv1.x + s1.y * tv1.y + s1.z * tv1.z + s1.w * tv1.w;
        #pragma unroll
        for (int o = 16; o > 0; o >>= 1)
            pd += __shfl_xor_sync(0xFFFFFFFFu, pd, o);

        float e = __expf(pd);
        den += e;
        U0.x += e * s0.x;
        U0.y += e * s0.y;
        U0.z += e * s0.z;
        U0.w += e * s0.w;
        U1.x += e * s1.x;
        U1.y += e * s1.y;
        U1.z += e * s1.z;
        U1.w += e * s1.w;
    }

    // combine halves through smem (one barrier per 4-row block)
    if (half == 1) {
        sU0[rl][lane] = U0;
        sU1[rl][lane] = U1;
        if (lane == 0) sden[rl] = den;
    }
    __syncthreads();

    if (half == 0) {
        float4 pU0 = sU0[rl][lane];
        float4 pU1 = sU1[rl][lane];
        float dtot = den + sden[rl];

        float4 o0 = {0.f, 0.f, 0.f, 0.f}, o1 = {0.f, 0.f, 0.f, 0.f};
        float ssum = 0.f;
        if (dtot > 0.f) {
            float inv = 1.f / dtot;
            o0.x = (U0.x + pU0.x) * inv; o0.y = (U0.y + pU0.y) * inv;
            o0.z = (U0.z + pU0.z) * inv; o0.w = (U0.w + pU0.w) * inv;
            o1.x = (U1.x + pU1.x) * inv; o1.y = (U1.y + pU1.y) * inv;
            o1.z = (U1.z + pU1.z) * inv; o1.w = (U1.w + pU1.w) * inv;
            ssum = 1.f;
        }
        float4* u4 = (float4*)(u + (size_t)gw * DD);
        u4[lane] = o0;
        u4[lane + 32] = o1;
        if (lane == 0) s_out[gw] = ssum;
    }
}

// ---------------------------------------------------------------------------
// Launch
// ---------------------------------------------------------------------------
extern "C" void kernel_launch(void* const* d_in, const int* in_sizes, int n_in,
                              void* d_out, int out_size) {
    const float* queries = (const float*)d_in[0];
    const float* feat    = (const float*)d_in[1];
    const float* coords  = (const float*)d_in[2];
    const int*   vmask   = (const int*)d_in[3];
    const float* Wq      = (const float*)d_in[4];
    const float* bq      = (const float*)d_in[5];
    const float* Wkv     = (const float*)d_in[6];
    const float* bkv     = (const float*)d_in[7];
    const float* Wo      = (const float*)d_in[8];
    const float* bo      = (const float*)d_in[9];
    const float* gamma   = (const float*)d_in[10];
    const float* beta    = (const float*)d_in[11];
    float* out = (float*)d_out;

    float *p_t, *p_u, *p_s, *p_Wqk, *p_Wvo, *p_bqk, *p_bvo;
    cudaGetSymbolAddress((void**)&p_t, g_t);
    cudaGetSymbolAddress((void**)&p_u, g_u);
    cudaGetSymbolAddress((void**)&p_s, g_s);
    cudaGetSymbolAddress((void**)&p_Wqk, g_Wqk);
    cudaGetSymbolAddress((void**)&p_Wvo, g_Wvo);
    cudaGetSymbolAddress((void**)&p_bqk, g_bqk);
    cudaGetSymbolAddress((void**)&p_bvo, g_bvo);

    const int Mq = BB * NN;   // 32768

    fold_kernel<<<513, 256>>>(Wq, bq, Wkv, bkv, Wo);
    // t = LN(queries) @ Wqk + bqk, scaled by 1/16, LN fused into A-load
    gemm3_kernel<true><<<dim3(DD / 128, Mq / 64), 256>>>(
        queries, p_Wqk, p_bqk, nullptr, nullptr, nullptr,
        gamma, beta, 0.0625f, p_t, Mq, DD, DD);
    // fused sample + attention (2 warps per row) -> u, s
    fused_attn_warp2<<<Mq / 4, 256>>>(feat, coords, vmask, p_t, p_u, p_s);
    // out = queries + u @ Wvo + s*bvo + bo
    gemm3_kernel<false><<<dim3(DD / 128, Mq / 64), 256>>>(
        p_u, p_Wvo, bo, queries, p_s, p_bvo,
        nullptr, nullptr, 1.0f, out, Mq, DD, DD);
}

// round 16
// speedup vs baseline: 1.1546x; 1.1286x over previous
#include <cuda_runtime.h>
#include <math.h>

// Problem constants
#define BB 2
#define NN 16384
#define CC 8
#define DD 256
#define HH 64
#define WW 64

// Scratch (device globals: allocation-free)
__device__ float g_t[(size_t)BB * NN * DD];      // t = LN(q) @ Wqk + bqk, scaled 1/16
__device__ float g_u[(size_t)BB * NN * DD];      // u = sum_c attn*sampled
__device__ float g_s[(size_t)BB * NN];           // sum of attn per row (0 or 1)
__device__ float g_Wqk[DD * DD];                 // Wq @ Wkv[:,:D]^T
__device__ float g_Wvo[DD * DD];                 // Wkv[:,D:] @ Wo
__device__ float g_bias2[DD];                    // Wkv[:, :D] . (bq + beta@Wq)
__device__ float g_gW1[DD];                      // (gamma@Wq) @ Wkv[:,:D]^T
__device__ float g_bvo[DD];                      // bv @ Wo

__device__ __forceinline__ void cp16(void* smem_dst, const void* gmem_src) {
    unsigned s = (unsigned)__cvta_generic_to_shared(smem_dst);
    asm volatile("cp.async.cg.shared.global [%0], [%1], 16;" :: "r"(s), "l"(gmem_src));
}
#define CP_COMMIT() asm volatile("cp.async.commit_group;")

// ---------------------------------------------------------------------------
// Weight folding (fp32, exact). 513 blocks x 256 threads.
// ---------------------------------------------------------------------------
__global__ void fold_kernel(const float* __restrict__ Wq,
                            const float* __restrict__ bq,
                            const float* __restrict__ Wkv,
                            const float* __restrict__ bkv,
                            const float* __restrict__ Wo,
                            const float* __restrict__ gamma,
                            const float* __restrict__ beta) {
    __shared__ float srow[DD];
    __shared__ float srow2[DD];
    int bidx = blockIdx.x;
    int tid = threadIdx.x;

    if (bidx < 256) {
        // Wqk[a][j] = sum_d Wq[a][d] * Wkv[j][d]
        srow[tid] = Wq[(size_t)bidx * DD + tid];
        __syncthreads();
        float acc = 0.f;
        const float* wr = Wkv + (size_t)tid * (2 * DD);
        #pragma unroll 4
        for (int d = 0; d < DD; d++) acc += srow[d] * wr[d];
        g_Wqk[(size_t)bidx * DD + tid] = acc;
    } else if (bidx < 512) {
        // Wvo[i][j] = sum_k Wkv[i][256+k] * Wo[k][j]
        int i = bidx - 256;
        srow[tid] = Wkv[(size_t)i * (2 * DD) + DD + tid];
        __syncthreads();
        float acc = 0.f;
        #pragma unroll 4
        for (int k = 0; k < DD; k++) acc += srow[k] * Wo[(size_t)k * DD + tid];
        g_Wvo[(size_t)i * DD + tid] = acc;
    } else {
        // gq[d] = sum_a gamma[a]*Wq[a][d];  vq[d] = bq[d] + sum_a beta[a]*Wq[a][d]
        float g1 = 0.f, b1 = 0.f;
        #pragma unroll 4
        for (int a = 0; a < DD; a++) {
            float w = Wq[(size_t)a * DD + tid];
            g1 += gamma[a] * w;
            b1 += beta[a] * w;
        }
        srow[tid] = g1;
        srow2[tid] = bq[tid] + b1;
        __syncthreads();
        // gW1[j] = sum_d gq[d]*Wkv[j][d];  bias2[j] = sum_d vq[d]*Wkv[j][d]
        float gw = 0.f, b2 = 0.f, a2 = 0.f;
        const float* wr = Wkv + (size_t)tid * (2 * DD);
        #pragma unroll 4
        for (int d = 0; d < DD; d++) {
            gw += srow[d] * wr[d];
            b2 += srow2[d] * wr[d];
        }
        #pragma unroll 4
        for (int k = 0; k < DD; k++) a2 += bkv[DD + k] * Wo[(size_t)k * DD + tid];
        g_gW1[tid] = gw;
        g_bias2[tid] = b2;
        g_bvo[tid] = a2;
    }
}

// ---------------------------------------------------------------------------
// TF32 tensor-core GEMM, BM=64 BN=128 BK=16, 256 threads (8 warps, 32x32 warp
// tiles), 3-stage cp.async pipeline, one __syncthreads per k-tile.
// Raw fp32 into tf32 MMA. A stored [m][k] LDA=20. K must be 256. 3 CTAs/SM.
//
// DO_LN variant (deferred LayerNorm, NO separate pre-pass):
//   A-tile stores x*gamma; row sums (s, s2) accumulated from the SAME
//   register-path loads the pipeline already does; quad-shfl at end gives
//   mu, rs per row, exchanged via smem; epilogue applies
//   t = scale*( rs*acc + bias2[c] - (rs*mu)*gW1[c] )   [bias=bias2, bvec2=gW1]
// Non-LN epilogue: C = scale*(A@W + bias [+ svec[r]*bvec2[c]]) [+ resid].
// ---------------------------------------------------------------------------
template <bool DO_LN>
__global__ void __launch_bounds__(256, 3)
gemm3_kernel(const float* __restrict__ A, const float* __restrict__ W,
             const float* __restrict__ bias, const float* __restrict__ resid,
             const float* __restrict__ svec, const float* __restrict__ bvec2,
             const float* __restrict__ gamma,
             float scale, float* __restrict__ Cm, int M, int K, int Nc) {
    const int BK = 16, LDA = 20, LDB = 136, NT = 16;   // NT = K/BK, K==256
    __shared__ unsigned As[3][64][LDA];
    __shared__ unsigned Bs[3][BK][LDB];
    __shared__ float sg[DD];
    __shared__ float s_rs[64], s_rm[64];

    int tid = threadIdx.x;
    int lane = tid & 31;
    int wid = tid >> 5;
    int wm = wid >> 2;
    int wn = wid & 3;
    int g = lane >> 2;
    int tg = lane & 3;

    size_t row0 = (size_t)blockIdx.y * 64;
    size_t col0 = (size_t)blockIdx.x * 128;

    int a_m = tid >> 2;
    int a_kq = tid & 3;
    int b_kk = tid >> 5;
    int b_nq = tid & 31;

    const float* Aptr = A + (row0 + a_m) * (size_t)K + a_kq * 4;
    const float* Bptr = W + (size_t)b_kk * Nc + col0 + b_nq * 4;

    float ls = 0.f, ls2 = 0.f;   // LN stats (DO_LN)
    if (DO_LN) {
        sg[tid] = gamma[tid];
        __syncthreads();   // sg visible to A-store of all threads
    }

    float acc[2][4][4];
    #pragma unroll
    for (int i = 0; i < 2; i++)
        #pragma unroll
        for (int j = 0; j < 4; j++)
            #pragma unroll
            for (int r = 0; r < 4; r++) acc[i][j][r] = 0.f;

#define LOADB(t, buf)                                                        \
    do {                                                                     \
        cp16(&Bs[buf][b_kk][b_nq * 4], Bptr + (size_t)((t) * BK) * Nc);      \
        cp16(&Bs[buf][b_kk + 8][b_nq * 4],                                   \
             Bptr + (size_t)((t) * BK + 8) * Nc);                            \
    } while (0)

#define LNACC(av)                                                            \
    do {                                                                     \
        ls += (av).x + (av).y + (av).z + (av).w;                             \
        ls2 += (av).x * (av).x + (av).y * (av).y + (av).z * (av).z           \
             + (av).w * (av).w;                                              \
    } while (0)

#define STORA_G(buf, av, t)                                                  \
    do {                                                                     \
        int kc = a_kq * 4, kg = (t) * BK + kc;                               \
        As[buf][a_m][kc + 0] = __float_as_uint((av).x * sg[kg + 0]);         \
        As[buf][a_m][kc + 1] = __float_as_uint((av).y * sg[kg + 1]);         \
        As[buf][a_m][kc + 2] = __float_as_uint((av).z * sg[kg + 2]);         \
        As[buf][a_m][kc + 3] = __float_as_uint((av).w * sg[kg + 3]);         \
    } while (0)

    // ---- prologue: tiles 0 and 1 committed
    if (DO_LN) {
        float4 av0 = *(const float4*)(Aptr);
        float4 av1 = *(const float4*)(Aptr + BK);
        LNACC(av0); LNACC(av1);
        LOADB(0, 0); CP_COMMIT();
        LOADB(1, 1); CP_COMMIT();
        STORA_G(0, av0, 0);
        STORA_G(1, av1, 1);
    } else {
        cp16(&As[0][a_m][a_kq * 4], Aptr);
        LOADB(0, 0); CP_COMMIT();
        cp16(&As[1][a_m][a_kq * 4], Aptr + BK);
        LOADB(1, 1); CP_COMMIT();
    }

    for (int kt = 0; kt < NT; kt++) {
        int pf = kt + 2;
        if (kt < NT - 1) asm volatile("cp.async.wait_group 1;");
        else             asm volatile("cp.async.wait_group 0;");
        __syncthreads();   // all warps done reading buf (kt-1)%3

        float4 av;
        if (pf < NT) {
            int buf = pf % 3;
            if (DO_LN) {
                av = *(const float4*)(Aptr + pf * BK);
                LNACC(av);
            } else {
                cp16(&As[buf][a_m][a_kq * 4], Aptr + pf * BK);
            }
            LOADB(pf, buf);
            CP_COMMIT();
        }

        int cur = kt % 3;
        #pragma unroll
        for (int ks = 0; ks < 2; ks++) {
            int kb = ks * 8;
            unsigned a[2][4], b[4][2];
            #pragma unroll
            for (int mt = 0; mt < 2; mt++) {
                int m = wm * 32 + mt * 16 + g;
                a[mt][0] = As[cur][m][kb + tg];
                a[mt][1] = As[cur][m + 8][kb + tg];
                a[mt][2] = As[cur][m][kb + tg + 4];
                a[mt][3] = As[cur][m + 8][kb + tg + 4];
            }
            #pragma unroll
            for (int nt = 0; nt < 4; nt++) {
                int n = wn * 32 + nt * 8 + g;
                b[nt][0] = Bs[cur][kb + tg][n];
                b[nt][1] = Bs[cur][kb + tg + 4][n];
            }
            #pragma unroll
            for (int mt = 0; mt < 2; mt++)
                #pragma unroll
                for (int nt = 0; nt < 4; nt++) {
                    asm volatile(
                        "mma.sync.aligned.m16n8k8.row.col.f32.tf32.tf32.f32 "
                        "{%0,%1,%2,%3}, {%4,%5,%6,%7}, {%8,%9}, {%0,%1,%2,%3};\n"
                        : "+f"(acc[mt][nt][0]), "+f"(acc[mt][nt][1]),
                          "+f"(acc[mt][nt][2]), "+f"(acc[mt][nt][3])
                        : "r"(a[mt][0]), "r"(a[mt][1]), "r"(a[mt][2]), "r"(a[mt][3]),
                          "r"(b[nt][0]), "r"(b[nt][1]));
                }
        }

        if (DO_LN && pf < NT) STORA_G(pf % 3, av, pf);
    }

    if (DO_LN) {
        // quad reduce (4 threads own one row), publish per-row LN factors
        ls += __shfl_xor_sync(0xFFFFFFFFu, ls, 1);
        ls += __shfl_xor_sync(0xFFFFFFFFu, ls, 2);
        ls2 += __shfl_xor_sync(0xFFFFFFFFu, ls2, 1);
        ls2 += __shfl_xor_sync(0xFFFFFFFFu, ls2, 2);
        float mu = ls * (1.f / (float)DD);
        float rs = rsqrtf(ls2 * (1.f / (float)DD) - mu * mu + 1e-5f);
        if (a_kq == 0) {
            s_rs[a_m] = rs;
            s_rm[a_m] = rs * mu;
        }
        __syncthreads();
    }

    // ---- epilogue
    #pragma unroll
    for (int mt = 0; mt < 2; mt++) {
        int ml = wm * 32 + mt * 16 + g;
        size_t r = row0 + ml;
        float r0s = 0.f, r0m = 0.f, r1s = 0.f, r1m = 0.f;
        if (DO_LN) {
            r0s = s_rs[ml]; r0m = s_rm[ml];
            r1s = s_rs[ml + 8]; r1m = s_rm[ml + 8];
        }
        #pragma unroll
        for (int nt = 0; nt < 4; nt++) {
            size_t c = col0 + wn * 32 + nt * 8 + tg * 2;
            float2 bb = *(const float2*)(bias + c);
            float2 v0, v1;
            if (DO_LN) {
                float2 gw = *(const float2*)(bvec2 + c);
                v0.x = (acc[mt][nt][0] * r0s + bb.x - r0m * gw.x) * scale;
                v0.y = (acc[mt][nt][1] * r0s + bb.y - r0m * gw.y) * scale;
                v1.x = (acc[mt][nt][2] * r1s + bb.x - r1m * gw.x) * scale;
                v1.y = (acc[mt][nt][3] * r1s + bb.y - r1m * gw.y) * scale;
            } else {
                v0.x = acc[mt][nt][0] + bb.x;
                v0.y = acc[mt][nt][1] + bb.y;
                v1.x = acc[mt][nt][2] + bb.x;
                v1.y = acc[mt][nt][3] + bb.y;
                if (svec) {
                    float2 b2 = *(const float2*)(bvec2 + c);
                    float s0 = svec[r], s1 = svec[r + 8];
                    v0.x += s0 * b2.x; v0.y += s0 * b2.y;
                    v1.x += s1 * b2.x; v1.y += s1 * b2.y;
                }
                v0.x *= scale; v0.y *= scale; v1.x *= scale; v1.y *= scale;
                if (resid) {
                    float2 r0 = *(const float2*)(resid + r * Nc + c);
                    float2 r1 = *(const float2*)(resid + (r + 8) * Nc + c);
                    v0.x += r0.x; v0.y += r0.y;
                    v1.x += r1.x; v1.y += r1.y;
                }
            }
            *(float2*)(Cm + r * Nc + c) = v0;
            *(float2*)(Cm + (r + 8) * Nc + c) = v1;
        }
    }
#undef LOADB
#undef LNACC
#undef STORA_G
}

// ---------------------------------------------------------------------------
// Warp-per-row fused sample + score + softmax + weighted sum. (round-11 best)
// No max subtraction (scores bounded: t pre-scaled by 1/sqrt(D)).
// 256 threads = 8 rows per block; zero smem, zero barriers.
// ---------------------------------------------------------------------------
__global__ void __launch_bounds__(256, 4)
fused_attn_warp(const float* __restrict__ feat,
                const float* __restrict__ coords,
                const int* __restrict__ vmask,
                const float* __restrict__ t,
                float* __restrict__ u,
                float* __restrict__ s_out) {
    int gw = (blockIdx.x << 3) | (threadIdx.x >> 5);   // global warp = row bn
    int lane = threadIdx.x & 31;
    int b = gw >> 14;              // NN = 16384
    int n = gw & (NN - 1);

    // hoist all 8 mask loads (independent LDGs)
    unsigned mbits = 0;
    #pragma unroll
    for (int c = 0; c < CC; c++)
        mbits |= (vmask[((size_t)(b * CC + c)) * NN + n] ? 1u : 0u) << c;

    const float4* t4 = (const float4*)(t + (size_t)gw * DD);
    float4 tv0 = t4[lane];
    float4 tv1 = t4[lane + 32];

    float4 U0 = {0.f, 0.f, 0.f, 0.f}, U1 = {0.f, 0.f, 0.f, 0.f};
    float den = 0.f;

    #pragma unroll
    for (int c = 0; c < CC; c++) {
        if (!((mbits >> c) & 1u)) continue;   // warp-uniform skip

        const float* pc = coords + ((size_t)(b * CC + c) * NN + n) * 2;
        float xf = (pc[0] + 1.f) * 0.5f * (float)(WW - 1);
        float yf = (pc[1] + 1.f) * 0.5f * (float)(HH - 1);
        float x0f = floorf(xf), y0f = floorf(yf);
        float wx = xf - x0f, wy = yf - y0f;
        int x0 = (int)x0f, y0 = (int)y0f;
        float w00 = (1.f - wy) * (1.f - wx);
        float w01 = (1.f - wy) * wx;
        float w10 = wy * (1.f - wx);
        float w11 = wy * wx;
        bool bx0 = (x0 >= 0) && (x0 < WW);
        bool bx1 = (x0 + 1 >= 0) && (x0 + 1 < WW);
        bool by0 = (y0 >= 0) && (y0 < HH);
        bool by1 = (y0 + 1 >= 0) && (y0 + 1 < HH);
        if (!(bx0 && by0)) w00 = 0.f;
        if (!(bx1 && by0)) w01 = 0.f;
        if (!(bx0 && by1)) w10 = 0.f;
        if (!(bx1 && by1)) w11 = 0.f;
        int xc0 = min(max(x0, 0), WW - 1);
        int xc1 = min(max(x0 + 1, 0), WW - 1);
        int yc0 = min(max(y0, 0), HH - 1);
        int yc1 = min(max(y0 + 1, 0), HH - 1);

        size_t fbase = (size_t)(b * CC + c) * HH * WW;
        const float4* f00 = (const float4*)(feat + (fbase + (size_t)yc0 * WW + xc0) * DD);
        const float4* f01 = (const float4*)(feat + (fbase + (size_t)yc0 * WW + xc1) * DD);
        const float4* f10 = (const float4*)(feat + (fbase + (size_t)yc1 * WW + xc0) * DD);
        const float4* f11 = (const float4*)(feat + (fbase + (size_t)yc1 * WW + xc1) * DD);

        // issue all 16 loads (independent); blend progressively per corner
        float4 a00 = f00[lane], a01 = f01[lane], a10 = f10[lane], a11 = f11[lane];
        float4 b00 = f00[lane + 32], b01 = f01[lane + 32],
               b10 = f10[lane + 32], b11 = f11[lane + 32];

        float4 s0, s1;
        s0.x = w00 * a00.x; s0.y = w00 * a00.y; s0.z = w00 * a00.z; s0.w = w00 * a00.w;
        s0.x += w01 * a01.x; s0.y += w01 * a01.y; s0.z += w01 * a01.z; s0.w += w01 * a01.w;
        s0.x += w10 * a10.x; s0.y += w10 * a10.y; s0.z += w10 * a10.z; s0.w += w10 * a10.w;
        s0.x += w11 * a11.x; s0.y += w11 * a11.y; s0.z += w11 * a11.z; s0.w += w11 * a11.w;
        s1.x = w00 * b00.x; s1.y = w00 * b00.y; s1.z = w00 * b00.z; s1.w = w00 * b00.w;
        s1.x += w01 * b01.x; s1.y += w01 * b01.y; s1.z += w01 * b01.z; s1.w += w01 * b01.w;
        s1.x += w10 * b10.x; s1.y += w10 * b10.y; s1.z += w10 * b10.z; s1.w += w10 * b10.w;
        s1.x += w11 * b11.x; s1.y += w11 * b11.y; s1.z += w11 * b11.z; s1.w += w11 * b11.w;

        float pd = s0.x * tv0.x + s0.y * tv0.y + s0.z * tv0.z + s0.w * tv0.w
                 + s1.x * tv1.x + s1.y * tv1.y + s1.z * tv1.z + s1.w * tv1.w;
        #pragma unroll
        for (int o = 16; o > 0; o >>= 1)
            pd += __shfl_xor_sync(0xFFFFFFFFu, pd, o);

        float e = __expf(pd);
        den += e;
        U0.x += e * s0.x;
        U0.y += e * s0.y;
        U0.z += e * s0.z;
        U0.w += e * s0.w;
        U1.x += e * s1.x;
        U1.y += e * s1.y;
        U1.z += e * s1.z;
        U1.w += e * s1.w;
    }

    float4 o0 = {0.f, 0.f, 0.f, 0.f}, o1 = {0.f, 0.f, 0.f, 0.f};
    float ssum = 0.f;
    if (den > 0.f) {
        float inv = 1.f / den;
        o0.x = U0.x * inv; o0.y = U0.y * inv; o0.z = U0.z * inv; o0.w = U0.w * inv;
        o1.x = U1.x * inv; o1.y = U1.y * inv; o1.z = U1.z * inv; o1.w = U1.w * inv;
        ssum = 1.f;
    }
    float4* u4 = (float4*)(u + (size_t)gw * DD);
    u4[lane] = o0;
    u4[lane + 32] = o1;
    if (lane == 0) s_out[gw] = ssum;
}

// ---------------------------------------------------------------------------
// Launch
// ---------------------------------------------------------------------------
extern "C" void kernel_launch(void* const* d_in, const int* in_sizes, int n_in,
                              void* d_out, int out_size) {
    const float* queries = (const float*)d_in[0];
    const float* feat    = (const float*)d_in[1];
    const float* coords  = (const float*)d_in[2];
    const int*   vmask   = (const int*)d_in[3];
    const float* Wq      = (const float*)d_in[4];
    const float* bq      = (const float*)d_in[5];
    const float* Wkv     = (const float*)d_in[6];
    const float* bkv     = (const float*)d_in[7];
    const float* Wo      = (const float*)d_in[8];
    const float* bo      = (const float*)d_in[9];
    const float* gamma   = (const float*)d_in[10];
    const float* beta    = (const float*)d_in[11];
    float* out = (float*)d_out;

    float *p_t, *p_u, *p_s, *p_Wqk, *p_Wvo, *p_bias2, *p_gW1, *p_bvo;
    cudaGetSymbolAddress((void**)&p_t, g_t);
    cudaGetSymbolAddress((void**)&p_u, g_u);
    cudaGetSymbolAddress((void**)&p_s, g_s);
    cudaGetSymbolAddress((void**)&p_Wqk, g_Wqk);
    cudaGetSymbolAddress((void**)&p_Wvo, g_Wvo);
    cudaGetSymbolAddress((void**)&p_bias2, g_bias2);
    cudaGetSymbolAddress((void**)&p_gW1, g_gW1);
    cudaGetSymbolAddress((void**)&p_bvo, g_bvo);

    const int Mq = BB * NN;   // 32768

    fold_kernel<<<513, 256>>>(Wq, bq, Wkv, bkv, Wo, gamma, beta);
    // t = ( rs*((q*gamma)@Wqk) + bias2 - rs*mu*gW1 ) / 16   (deferred LN)
    gemm3_kernel<true><<<dim3(DD / 128, Mq / 64), 256>>>(
        queries, p_Wqk, p_bias2, nullptr, nullptr, p_gW1,
        gamma, 0.0625f, p_t, Mq, DD, DD);
    // fused sample + attention (warp per row) -> u, s
    fused_attn_warp<<<Mq / 8, 256>>>(feat, coords, vmask, p_t, p_u, p_s);
    // out = queries + u @ Wvo + s*bvo + bo
    gemm3_kernel<false><<<dim3(DD / 128, Mq / 64), 256>>>(
        p_u, p_Wvo, bo, queries, p_s, p_bvo,
        nullptr, 1.0f, out, Mq, DD, DD);
}